// round 6
// baseline (speedup 1.0000x reference)
#include <cuda_runtime.h>
#include <cstdint>
#include <math.h>

// Problem constants
#define G  8
#define T  4096
#define H  1024
#define E  32
#define C  64
#define GT (G*T)                       // 32768 tokens
#define GTEC ((size_t)G*(size_t)T*(size_t)E*(size_t)C)   // 67,108,864

// GEMM tiling: 128 tokens per block, 128 threads
#define MTILE 128
#define KTILE 32
#define NKC   (H/KTILE)                // 32 k-chunks
#define XP    (MTILE+1)
#define GEMM_BLOCKS (GT/MTILE)         // 256
#define K1THREADS 128
#define ZERO_BLOCKS 2048

#define NTHREADS 256                   // k2 block size

// Scratch (device globals; no allocations allowed)
__device__ float g_probs[G*E*T];       // probs transposed [g][e][t], 4 MB
__device__ float g_zpart[GEMM_BLOCKS];

// ---------------------------------------------------------------------------
// Kernel 1 (fused): bid<256  -> double-buffered GEMM + softmax + z partials
//                   bid>=256 -> streaming zero-fill of out (536 MB)
// GEMM is FMA/L1-bound (17% DRAM), memset is DRAM-write-bound (60%):
// disjoint resources, so they overlap instead of serializing.
// ---------------------------------------------------------------------------
__global__ __launch_bounds__(K1THREADS)
void router_k1(const float* __restrict__ x,   // [G,T,H]
               const float* __restrict__ Wm,  // [H,E]
               const float* __restrict__ bv,  // [E]
               float* __restrict__ out)
{
    const int bid = blockIdx.x;
    const int tid = threadIdx.x;

    if (bid >= GEMM_BLOCKS) {
        // ---- zero-fill path: evict-streaming 16B stores ----
        uint4 z; z.x = 0u; z.y = 0u; z.z = 0u; z.w = 0u;
        uint4* o4 = reinterpret_cast<uint4*>(out);
        const size_t n4 = (2*GTEC) / 4;                    // 33,554,432
        size_t i = (size_t)(bid - GEMM_BLOCKS) * K1THREADS + tid;
        const size_t stride = (size_t)ZERO_BLOCKS * K1THREADS;
        for (; i < n4; i += stride) __stcs(o4 + i, z);
        return;
    }

    // ---- GEMM path ----
    __shared__ __align__(16) float xs[KTILE * XP];
    __shared__ __align__(16) float ws[KTILE * E];
    __shared__ float zred[K1THREADS];

    const int gtBase = bid * MTILE;
    const float* xbase = x + (size_t)gtBase * H;

    unsigned long long acc[16];
#pragma unroll
    for (int i = 0; i < 16; i++) acc[i] = 0ull;

    float4 pfx[8];
    float4 pfw[2];
#pragma unroll
    for (int r = 0; r < 8; r++) {
        int s  = r * K1THREADS + tid;
        int tl = s >> 3;
        int k4 = s & 7;
        pfx[r] = __ldcs(reinterpret_cast<const float4*>(xbase + (size_t)tl * H + k4 * 4));
    }
#pragma unroll
    for (int r = 0; r < 2; r++)
        pfw[r] = *reinterpret_cast<const float4*>(Wm + (r * K1THREADS + tid) * 4);

    for (int kc = 0; kc < NKC; kc++) {
        __syncthreads();
#pragma unroll
        for (int r = 0; r < 8; r++) {
            int s  = r * K1THREADS + tid;
            int tl = s >> 3;
            int k4 = s & 7;
            xs[(k4 * 4 + 0) * XP + tl] = pfx[r].x;
            xs[(k4 * 4 + 1) * XP + tl] = pfx[r].y;
            xs[(k4 * 4 + 2) * XP + tl] = pfx[r].z;
            xs[(k4 * 4 + 3) * XP + tl] = pfx[r].w;
        }
#pragma unroll
        for (int r = 0; r < 2; r++)
            *reinterpret_cast<float4*>(ws + (r * K1THREADS + tid) * 4) = pfw[r];
        __syncthreads();

        if (kc + 1 < NKC) {
            const float* xn = xbase + (kc + 1) * KTILE;
#pragma unroll
            for (int r = 0; r < 8; r++) {
                int s  = r * K1THREADS + tid;
                int tl = s >> 3;
                int k4 = s & 7;
                pfx[r] = __ldcs(reinterpret_cast<const float4*>(xn + (size_t)tl * H + k4 * 4));
            }
            const float* wn = Wm + (kc + 1) * KTILE * E;
#pragma unroll
            for (int r = 0; r < 2; r++)
                pfw[r] = *reinterpret_cast<const float4*>(wn + (r * K1THREADS + tid) * 4);
        }

#pragma unroll
        for (int kk = 0; kk < KTILE; kk++) {
            const float xv = xs[kk * XP + tid];
            unsigned long long xx;
            asm("mov.b64 %0, {%1,%1};" : "=l"(xx) : "r"(__float_as_uint(xv)));
            const ulonglong2* wr = reinterpret_cast<const ulonglong2*>(ws + kk * E);
#pragma unroll
            for (int q = 0; q < 8; q++) {
                ulonglong2 wp = wr[q];
                asm("fma.rn.f32x2 %0, %1, %2, %0;"
                    : "+l"(acc[2*q])   : "l"(xx), "l"(wp.x));
                asm("fma.rn.f32x2 %0, %1, %2, %0;"
                    : "+l"(acc[2*q+1]) : "l"(xx), "l"(wp.y));
            }
        }
    }

    // ---- epilogue: bias, softmax, transposed prob write, z partial ----
    float l[E];
#pragma unroll
    for (int i = 0; i < 16; i++) {
        float2 f = *reinterpret_cast<float2*>(&acc[i]);
        l[2*i]   = f.x;
        l[2*i+1] = f.y;
    }
#pragma unroll
    for (int e = 0; e < E; e++) l[e] += __ldg(&bv[e]);

    float m = l[0];
#pragma unroll
    for (int e = 1; e < E; e++) m = fmaxf(m, l[e]);
    float s = 0.f;
#pragma unroll
    for (int e = 0; e < E; e++) { l[e] = expf(l[e] - m); s += l[e]; }
    const float inv = 1.f / s;

    const int token = gtBase + tid;
    const int g  = token >> 12;
    const int tt = token & (T - 1);
    float* pr = g_probs + (size_t)g * E * T + tt;
#pragma unroll
    for (int e = 0; e < E; e++) pr[(size_t)e * T] = l[e] * inv;

    const float lse = m + logf(s);
    zred[tid] = lse * lse;
    __syncthreads();
    for (int st = K1THREADS / 2; st > 0; st >>= 1) {
        if (tid < st) zred[tid] += zred[tid + st];
        __syncthreads();
    }
    if (tid == 0) g_zpart[bid] = zred[0];
}

// ---------------------------------------------------------------------------
// Kernel 2: per-(g,e) iterative top-C, scattering winners directly into the
// (already zeroed) combine/dispatch. Block 256 finalizes z-loss.
// Tie-break matches jax.lax.top_k: equal value -> lower token index.
// ---------------------------------------------------------------------------
__global__ __launch_bounds__(NTHREADS)
void router_k2(float* __restrict__ out)
{
    const int bid = blockIdx.x;
    const int tid = threadIdx.x;

    if (bid == G * E) {
        if (tid == 0) {
            float s = 0.f;
            for (int i = 0; i < GEMM_BLOCKS; i++) s += g_zpart[i];
            out[2 * GTEC] = s / (float)GT;
        }
        return;
    }

    float* combine  = out;
    float* dispatch = out + GTEC;

    const int g = bid >> 5;
    const int e = bid & (E - 1);
    const float* row = g_probs + (size_t)bid * T;

    float v[16];
#pragma unroll
    for (int j = 0; j < 16; j++) v[j] = row[tid + j * NTHREADS];

    float bvv = -INFINITY; int bt = tid;
#pragma unroll
    for (int j = 0; j < 16; j++)
        if (v[j] > bvv) { bvv = v[j]; bt = j * NTHREADS + tid; }

    __shared__ float swv[8];
    __shared__ int   swt[8];
    __shared__ int   wint;

    const int lane = tid & 31;
    const int wrp  = tid >> 5;

    for (int c = 0; c < C; c++) {
        float rv = bvv; int rt = bt;
#pragma unroll
        for (int off = 16; off; off >>= 1) {
            float ov = __shfl_xor_sync(0xffffffffu, rv, off);
            int   oi = __shfl_xor_sync(0xffffffffu, rt, off);
            if (ov > rv || (ov == rv && oi < rt)) { rv = ov; rt = oi; }
        }
        if (lane == 0) { swv[wrp] = rv; swt[wrp] = rt; }
        __syncthreads();
        if (tid == 0) {
            float Rv = swv[0]; int Rt = swt[0];
            for (int w = 1; w < 8; w++)
                if (swv[w] > Rv || (swv[w] == Rv && swt[w] < Rt)) {
                    Rv = swv[w]; Rt = swt[w];
                }
            wint = Rt;
            const size_t off = (((size_t)(g * T + Rt)) * E + e) * C + c;
            combine[off]  = Rv;
            dispatch[off] = 1.0f;
        }
        __syncthreads();
        const int wt = wint;
        if ((wt & (NTHREADS - 1)) == tid) {
            v[wt >> 8] = -INFINITY;
            bvv = -INFINITY; bt = tid;
#pragma unroll
            for (int j = 0; j < 16; j++)
                if (v[j] > bvv) { bvv = v[j]; bt = j * NTHREADS + tid; }
        }
    }
}

__global__ void nop_k() {}

// ---------------------------------------------------------------------------
extern "C" void kernel_launch(void* const* d_in, const int* in_sizes, int n_in,
                              void* d_out, int out_size)
{
    const float* x  = (const float*)d_in[0];
    const float* Wm = (const float*)d_in[1];
    const float* bv = (const float*)d_in[2];
    float* out = (float*)d_out;

    // harness launches 2 first; 3 nops put router_k1 at global idx 5 for ncu
    nop_k<<<1, 32>>>();
    nop_k<<<1, 32>>>();
    nop_k<<<1, 32>>>();
    router_k1<<<GEMM_BLOCKS + ZERO_BLOCKS, K1THREADS>>>(x, Wm, bv, out);
    router_k2<<<G * E + 1, NTHREADS>>>(out);
}